// round 13
// baseline (speedup 1.0000x reference)
#include <cuda_runtime.h>

// Sineconv: out[b,l,f] = sum_{w=0}^{64} x[b, l + 2f + ((f+w)>>5)] * sines[f, l+w]
//                        + x[b, l+32] * res_kernel[f]
// sines[f,s] = amplitude[f] * sin( ((frequency[f]*19000)*2pi) * sine_range[s] + phases[f]*2pi )
//
// x factor is piecewise-constant in w over 3 ranges -> each output needs
// 3 contiguous range-sums of sines (local fp32 prefix scan) + residual.
//
// R13: 2 tiles per CTA (ILP, not TLP). Evidence: a kernel with NO sines/scan
// ran 8.2us while full compute ran 7.4 -> floor is the lockstep phase
// structure (all warps chip-wide in the same load/scan/barrier/store phase).
// Each CTA owns tiles 2bx, 2bx+1: all 4 LDG.128 issued up front, sines A+B,
// the two scan shfl-chains interleaved, ONE barrier, epilogues A+B.
// 512 CTAs (smaller wall gap), guards only on CTA 127's tile B.

#define S_TOTAL 16384
#define L_OUT   16320
#define F_N     32
#define B_N     4
#define TILE_L  64
#define FG      8               // features per block
#define NPP     132             // Psh row stride (16B-aligned rows, CF epilogue)
#define XW      132             // xsh row stride (only 0..127 used)

// Accurate sinf via fp32 FMA Cody-Waite (exact internal products).
// |arg| <= ~1e5 here: total reduction error ~6e-8 rad.
__device__ __forceinline__ float acc_sinf(float a) {
    float kf = rintf(a * 0.63661977236758134f);          // 2/pi
    float r  = fmaf(-kf, 1.57079637050628662e+0f, a);    // c1 = float(pi/2)
    r        = fmaf(-kf, -4.37113900018624283e-8f, r);   // c2 = float(pi/2 - c1)
    int   q  = (int)kf;
    float r2 = r * r;
    float sp = fmaf(r2, fmaf(r2, fmaf(r2, -1.9841269841e-4f, 8.3333333333e-3f),
                             -1.6666666667e-1f), 1.0f);
    float s  = r * sp;
    float c  = fmaf(r2, fmaf(r2, fmaf(r2, fmaf(r2, 2.4801587302e-5f, -1.3888888889e-3f),
                             4.1666666667e-2f), -5.0e-1f), 1.0f);
    float v = (q & 1) ? c : s;
    return (q & 2) ? -v : v;
}

__global__ __launch_bounds__(256, 4) void sineconv_kernel(
    const float* __restrict__ x,          // (B, S, 1)
    const float* __restrict__ sr,         // (S,)
    const float* __restrict__ phases,     // (32,)
    const float* __restrict__ amplitude,  // (32,)
    const float* __restrict__ frequency,  // (32,)
    const float* __restrict__ res_kernel, // (32,)
    float* __restrict__ out)              // (B, L, F)
{
    __shared__ __align__(16) float PshA[FG][NPP];
    __shared__ __align__(16) float PshB[FG][NPP];
    __shared__ __align__(16) float xshA[B_N][XW];
    __shared__ __align__(16) float xshB[B_N][XW];

    const int tid  = threadIdx.x;
    const int lane = tid & 31;
    const int warp = tid >> 5;
    const int s0a  = blockIdx.x * (2 * TILE_L);    // tile A start
    const int s0b  = s0a + TILE_L;                 // tile B start
    const int fg0  = blockIdx.y * FG;

    // ================= front-batched loads (A always in bounds; B guarded) ====
    // sr windows: 4 samples/lane, one LDG.128 each. s0a+127 <= 16383 always.
    const float4 svA = ((const float4*)(sr + s0a))[lane];
    float4 svB = make_float4(0.f, 0.f, 0.f, 0.f);
    if (s0b + 4 * lane + 3 < S_TOTAL)
        svB = ((const float4*)(sr + s0b))[lane];

    // x halos: 128 floats per batch per tile; tid<128 -> 1 LDG.128 per tile.
    float4 xvA = make_float4(0.f, 0.f, 0.f, 0.f);
    float4 xvB = xvA;
    int xb_ = 0, xj = 0;
    if (tid < 128) {
        xb_ = tid >> 5;
        xj  = tid & 31;
        xvA = ((const float4*)(x + xb_ * S_TOTAL + s0a))[xj];
        if (s0b + 4 * xj + 3 < S_TOTAL)
            xvB = ((const float4*)(x + xb_ * S_TOTAL + s0b))[xj];
    }

    // ================= sines for both tiles; warp w owns feature row fg0+w ====
    {
        const float TWO_PI = 6.28318530717958647692f;
        const int f = fg0 + warp;
        // Replicate reference fp32 rounding: ((freq*19000)*2pi)*sr + ph
        float w2  = __fmul_rn(__fmul_rn(frequency[f], 19000.0f), TWO_PI);
        float ph  = __fmul_rn(phases[f], TWO_PI);
        float amp = amplitude[f];

        float a0 = __fmul_rn(amp, acc_sinf(__fadd_rn(__fmul_rn(w2, svA.x), ph)));
        float a1 = __fmul_rn(amp, acc_sinf(__fadd_rn(__fmul_rn(w2, svA.y), ph)));
        float a2 = __fmul_rn(amp, acc_sinf(__fadd_rn(__fmul_rn(w2, svA.z), ph)));
        float a3 = __fmul_rn(amp, acc_sinf(__fadd_rn(__fmul_rn(w2, svA.w), ph)));
        float b0 = __fmul_rn(amp, acc_sinf(__fadd_rn(__fmul_rn(w2, svB.x), ph)));
        float b1 = __fmul_rn(amp, acc_sinf(__fadd_rn(__fmul_rn(w2, svB.y), ph)));
        float b2 = __fmul_rn(amp, acc_sinf(__fadd_rn(__fmul_rn(w2, svB.z), ph)));
        float b3 = __fmul_rn(amp, acc_sinf(__fadd_rn(__fmul_rn(w2, svB.w), ph)));

        float lA0 = a0, lA1 = lA0 + a1, lA2 = lA1 + a2, runA = lA2 + a3;
        float lB0 = b0, lB1 = lB0 + b1, lB2 = lB1 + b2, runB = lB2 + b3;

        // two independent exclusive warp scans, interleaved (hides shfl latency)
        float tA = runA, tB = runB;
#pragma unroll
        for (int off = 1; off < 32; off <<= 1) {
            float nA = __shfl_up_sync(0xFFFFFFFFu, tA, off);
            float nB = __shfl_up_sync(0xFFFFFFFFu, tB, off);
            if (lane >= off) { tA += nA; tB += nB; }
        }
        float exA = tA - runA;
        float exB = tB - runB;

        float4 wA, wB;
        wA.x = exA;       wA.y = exA + lA0; wA.z = exA + lA1; wA.w = exA + lA2;
        wB.x = exB;       wB.y = exB + lB0; wB.z = exB + lB1; wB.w = exB + lB2;
        *((float4*)&PshA[warp][4 * lane]) = wA;
        *((float4*)&PshB[warp][4 * lane]) = wB;
        if (lane == 31) {
            PshA[warp][128] = exA + runA;
            PshB[warp][128] = exB + runB;
        }
    }
    // stage x (values long since landed)
    if (tid < 128) {
        *((float4*)&xshA[xb_][4 * xj]) = xvA;
        *((float4*)&xshB[xb_][4 * xj]) = xvB;
    }
    __syncthreads();

    // ================= epilogues: fl = tid&7, i0 = tid>>3 ======================
    const int fl = tid & 7;
    const int f  = fg0 + fl;
    const int i0 = tid >> 3;             // 0..31
    const float rk = res_kernel[f];
    const int i32 = 32 - f;
    const int i64 = 64 - f;
    const int xoff = 2 * f;

    // ---- tile A (always fully in range) ----
#pragma unroll
    for (int p = 0; p < 2; p++) {
        int i = i0 + p * 32;
        int l = s0a + i;
        float p0 = PshA[fl][i];
        float pa = PshA[fl][i + i32];
        float pb = PshA[fl][i + i64];
        float p3 = PshA[fl][i + 65];
        float A0 = pa - p0;
        float A1 = pb - pa;
        float A2 = p3 - pb;
        int xb2 = i + xoff;
#pragma unroll
        for (int b = 0; b < B_N; b++) {
            float r = fmaf(xshA[b][xb2],     A0,
                      fmaf(xshA[b][xb2 + 1], A1,
                      fmaf(xshA[b][xb2 + 2], A2,
                           xshA[b][i + 32] * rk)));
            out[(b * L_OUT + l) * F_N + f] = r;
        }
    }
    // ---- tile B (stores guarded; only CTA 127 clips) ----
#pragma unroll
    for (int p = 0; p < 2; p++) {
        int i = i0 + p * 32;
        int l = s0b + i;
        float p0 = PshB[fl][i];
        float pa = PshB[fl][i + i32];
        float pb = PshB[fl][i + i64];
        float p3 = PshB[fl][i + 65];
        float A0 = pa - p0;
        float A1 = pb - pa;
        float A2 = p3 - pb;
        int xb2 = i + xoff;
        if (l < L_OUT) {
#pragma unroll
            for (int b = 0; b < B_N; b++) {
                float r = fmaf(xshB[b][xb2],     A0,
                          fmaf(xshB[b][xb2 + 1], A1,
                          fmaf(xshB[b][xb2 + 2], A2,
                               xshB[b][i + 32] * rk)));
                out[(b * L_OUT + l) * F_N + f] = r;
            }
        }
    }
}

extern "C" void kernel_launch(void* const* d_in, const int* in_sizes, int n_in,
                              void* d_out, int out_size) {
    const float* x    = (const float*)d_in[0];
    const float* sr   = (const float*)d_in[1];
    const float* ph   = (const float*)d_in[2];
    const float* amp  = (const float*)d_in[3];
    const float* freq = (const float*)d_in[4];
    const float* rk   = (const float*)d_in[5];
    float* out = (float*)d_out;

    dim3 grid(128, F_N / FG);   // 128 CTAs x 2 tiles = 256 tiles >= 255
    sineconv_kernel<<<grid, 256>>>(x, sr, ph, amp, freq, rk, out);
}

// round 14
// speedup vs baseline: 1.0295x; 1.0295x over previous
#include <cuda_runtime.h>

// Sineconv: out[b,l,f] = sum_{w=0}^{64} x[b, l + 2f + ((f+w)>>5)] * sines[f, l+w]
//                        + x[b, l+32] * res_kernel[f]
// sines[f,s] = amplitude[f] * sin( ((frequency[f]*19000)*2pi) * sine_range[s] + phases[f]*2pi )
//
// x factor is piecewise-constant in w over 3 ranges -> each output needs
// 3 contiguous range-sums of sines (local fp32 prefix scan) + residual.
//
// R14: R9's per-warp machinery (empirical optimum: kernel pinned 7.4-7.9us
// across all 13 designs; R9 = 7.42 best) at HALF the CTA count to shrink the
// wall-kernel gap (ledger: ~1.5us @1020 CTAs, ~0.75us @512). 512 threads,
// FG=16, grid (255,2) = 510 CTAs, warps/SM ~55 (R9-level), single wave at
// 4 CTAs/SM. Epilogue fl=tid&15: stores become 2x64B segments per STG.

#define S_TOTAL 16384
#define L_OUT   16320
#define F_N     32
#define B_N     4
#define TILE_L  64
#define FG      16              // features per block
#define NPP     132             // Psh row stride (16B-aligned rows)
#define XW      132             // xsh row stride (only 0..127 used)

// Accurate sinf via fp32 FMA Cody-Waite (exact internal products).
// |arg| <= ~1e5 here: total reduction error ~6e-8 rad.
__device__ __forceinline__ float acc_sinf(float a) {
    float kf = rintf(a * 0.63661977236758134f);          // 2/pi
    float r  = fmaf(-kf, 1.57079637050628662e+0f, a);    // c1 = float(pi/2)
    r        = fmaf(-kf, -4.37113900018624283e-8f, r);   // c2 = float(pi/2 - c1)
    int   q  = (int)kf;
    float r2 = r * r;
    float sp = fmaf(r2, fmaf(r2, fmaf(r2, -1.9841269841e-4f, 8.3333333333e-3f),
                             -1.6666666667e-1f), 1.0f);
    float s  = r * sp;
    float c  = fmaf(r2, fmaf(r2, fmaf(r2, fmaf(r2, 2.4801587302e-5f, -1.3888888889e-3f),
                             4.1666666667e-2f), -5.0e-1f), 1.0f);
    float v = (q & 1) ? c : s;
    return (q & 2) ? -v : v;
}

__global__ __launch_bounds__(512, 4) void sineconv_kernel(
    const float* __restrict__ x,          // (B, S, 1)
    const float* __restrict__ sr,         // (S,)
    const float* __restrict__ phases,     // (32,)
    const float* __restrict__ amplitude,  // (32,)
    const float* __restrict__ frequency,  // (32,)
    const float* __restrict__ res_kernel, // (32,)
    float* __restrict__ out)              // (B, L, F)
{
    __shared__ __align__(16) float Psh[FG][NPP];  // Psh[w][j] = excl prefix before sample j
    __shared__ __align__(16) float xsh[B_N][XW];

    const int tid  = threadIdx.x;
    const int lane = tid & 31;
    const int warp = tid >> 5;       // 0..15
    const int s0   = blockIdx.x * TILE_L;
    const int fg0  = blockIdx.y * FG;

    // ---- stage x: exactly 128 floats per batch (max index read = 127).
    // tid<128: one LDG.128 + one STS.128. Always in-bounds (s0+127 <= 16383).
    if (tid < 128) {
        int b = tid >> 5;
        int j = tid & 31;
        float4 v = ((const float4*)(x + b * S_TOTAL + s0))[j];
        *((float4*)&xsh[b][4 * j]) = v;
    }

    // ---- sines + fp32 prefix scan; warp w owns feature row fg0+w ----
    {
        const float TWO_PI = 6.28318530717958647692f;
        const int f = fg0 + warp;
        // Replicate reference fp32 rounding: ((freq*19000)*2pi)*sr + ph
        float w2  = __fmul_rn(__fmul_rn(frequency[f], 19000.0f), TWO_PI);
        float ph  = __fmul_rn(phases[f], TWO_PI);
        float amp = amplitude[f];

        // lane's 4 consecutive samples via one LDG.128 (s0+127 <= 16383 always)
        float4 sv = ((const float4*)(sr + s0))[lane];
        float v0 = __fmul_rn(amp, acc_sinf(__fadd_rn(__fmul_rn(w2, sv.x), ph)));
        float v1 = __fmul_rn(amp, acc_sinf(__fadd_rn(__fmul_rn(w2, sv.y), ph)));
        float v2 = __fmul_rn(amp, acc_sinf(__fadd_rn(__fmul_rn(w2, sv.z), ph)));
        float v3 = __fmul_rn(amp, acc_sinf(__fadd_rn(__fmul_rn(w2, sv.w), ph)));
        float loc0 = v0;
        float loc1 = loc0 + v1;
        float loc2 = loc1 + v2;
        float run  = loc2 + v3;
        // exclusive scan of lane totals across the warp
        float t = run;
#pragma unroll
        for (int off = 1; off < 32; off <<= 1) {
            float n = __shfl_up_sync(0xFFFFFFFFu, t, off);
            if (lane >= off) t += n;
        }
        float excl = t - run;     // exclusive prefix before sample 4*lane
        // one aligned STS.128: exclusive prefixes at indices 4*lane .. 4*lane+3
        float4 w4;
        w4.x = excl;
        w4.y = excl + loc0;
        w4.z = excl + loc1;
        w4.w = excl + loc2;
        *((float4*)&Psh[warp][4 * lane]) = w4;
        if (lane == 31) Psh[warp][128] = excl + run;   // max index read is 128
    }
    __syncthreads();

    // ---- epilogue: thread -> (fl = tid&15, i0 = tid>>4), 2 l-passes x 4 batches ----
    const int fl = tid & 15;
    const int f  = fg0 + fl;
    const int i0 = tid >> 4;             // 0..31
    const float rk = res_kernel[f];
    const int i32 = 32 - f;
    const int i64 = 64 - f;

#pragma unroll
    for (int p = 0; p < 2; p++) {
        int i = i0 + p * 32;             // local l index, 0..63
        int l = s0 + i;                  // grid exact: l < L_OUT always
        float p0 = Psh[fl][i];
        float pa = Psh[fl][i + i32];
        float pb = Psh[fl][i + i64];
        float p3 = Psh[fl][i + 65];
        float A0 = pa - p0;              // sum sines[f, l .. l+31-f]
        float A1 = pb - pa;              // sum sines[f, l+32-f .. l+63-f]
        float A2 = p3 - pb;              // sum sines[f, l+64-f .. l+64]
        int xb = i + 2 * f;
#pragma unroll
        for (int b = 0; b < B_N; b++) {
            float r = fmaf(xsh[b][xb],     A0,
                      fmaf(xsh[b][xb + 1], A1,
                      fmaf(xsh[b][xb + 2], A2,
                           xsh[b][i + 32] * rk)));
            out[(b * L_OUT + l) * F_N + f] = r;
        }
    }
}

extern "C" void kernel_launch(void* const* d_in, const int* in_sizes, int n_in,
                              void* d_out, int out_size) {
    const float* x    = (const float*)d_in[0];
    const float* sr   = (const float*)d_in[1];
    const float* ph   = (const float*)d_in[2];
    const float* amp  = (const float*)d_in[3];
    const float* freq = (const float*)d_in[4];
    const float* rk   = (const float*)d_in[5];
    float* out = (float*)d_out;

    dim3 grid(L_OUT / TILE_L, F_N / FG);   // (255, 2) = 510 CTAs
    sineconv_kernel<<<grid, 512>>>(x, sr, ph, amp, freq, rk, out);
}